// round 2
// baseline (speedup 1.0000x reference)
#include <cuda_runtime.h>
#include <cstdint>

#define B_ 8
#define V_ 8192
#define N_ 2048
#define C_ 128

typedef unsigned long long ull;

// ---------- f32x2 helpers (sm_100+ packed fp32: SASS FFMA2/FADD2/FMUL2) ----------
__device__ __forceinline__ ull pk2(float lo, float hi) {
    ull r; asm("mov.b64 %0, {%1, %2};" : "=l"(r) : "f"(lo), "f"(hi)); return r;
}
__device__ __forceinline__ void upk2(ull v, float& lo, float& hi) {
    asm("mov.b64 {%0, %1}, %2;" : "=f"(lo), "=f"(hi) : "l"(v));
}
__device__ __forceinline__ ull ffma2(ull a, ull b, ull c) {
    ull d; asm("fma.rn.f32x2 %0, %1, %2, %3;" : "=l"(d) : "l"(a), "l"(b), "l"(c)); return d;
}
__device__ __forceinline__ ull fmul2(ull a, ull b) {
    ull d; asm("mul.rn.f32x2 %0, %1, %2;" : "=l"(d) : "l"(a), "l"(b)); return d;
}
__device__ __forceinline__ ull fadd2(ull a, ull b) {
    ull d; asm("add.rn.f32x2 %0, %1, %2;" : "=l"(d) : "l"(a), "l"(b)); return d;
}

// ---------- device scratch (no allocations allowed) ----------
__device__ float g_buf[B_ * N_];            // g[b,n] = MLP(processed[b,n])
__device__ ull   W1p[64 * 128];             // packed W1 rows: {W1[2c2][d], W1[2c2+1][d]}
__device__ float cand_val[2 * B_ * V_];     // per n-half best d2
__device__ int   cand_idx[2 * B_ * V_];     // per n-half best index (global n)

// =====================================================================
// Kernel P: pack W1 row pairs for f32x2 consumption.
// =====================================================================
__global__ void kernelP(const float* __restrict__ W1) {
    int i = blockIdx.x * 256 + threadIdx.x;     // 8192 entries
    int c2 = i >> 7, d = i & 127;
    W1p[i] = pk2(W1[(2 * c2) * C_ + d], W1[(2 * c2 + 1) * C_ + d]);
}

// =====================================================================
// Kernel A: g[b,n] table.  grid=128 blocks (128 rows each), 512 threads.
// Each thread: 4 rows x 8 outputs, accumulating over c in f32x2 pairs.
// =====================================================================
__global__ void __launch_bounds__(512, 1)
kernelA(const float* __restrict__ processed,
        const float* __restrict__ b1,
        const float* __restrict__ W2,
        const float* __restrict__ b2) {
    extern __shared__ float Xs[];            // [128][128]
    __shared__ float red[128][17];

    const int t = threadIdx.x;
    const int rowBase = blockIdx.x * 128;

    const float4* src = (const float4*)(processed + (size_t)rowBase * C_);
    float4* dst = (float4*)Xs;
#pragma unroll
    for (int k = 0; k < 8; k++) {
        int idx4 = t + k * 512;
        dst[idx4] = src[idx4];
    }
    __syncthreads();

    const int tr = t >> 4;      // 0..31 -> 4 rows each
    const int td = t & 15;      // 0..15 -> 8 outputs each
    const int r0 = tr * 4;
    const int d0 = td * 8;

    ull acc[4][8];
#pragma unroll
    for (int i = 0; i < 4; i++)
#pragma unroll
        for (int j = 0; j < 8; j++) acc[i][j] = 0ull;

    const ulonglong2* Wv = (const ulonglong2*)W1p;
#pragma unroll 4
    for (int c2 = 0; c2 < 64; c2++) {
        ull x2[4];
#pragma unroll
        for (int i = 0; i < 4; i++)
            x2[i] = *(const ull*)&Xs[(r0 + i) * 128 + 2 * c2];
        ull w2[8];
#pragma unroll
        for (int j = 0; j < 4; j++) {
            ulonglong2 w = Wv[(c2 * 128 + d0) / 2 + j];
            w2[2 * j] = w.x; w2[2 * j + 1] = w.y;
        }
#pragma unroll
        for (int i = 0; i < 4; i++)
#pragma unroll
            for (int j = 0; j < 8; j++)
                acc[i][j] = ffma2(x2[i], w2[j], acc[i][j]);
    }

    float part[4] = {0.f, 0.f, 0.f, 0.f};
#pragma unroll
    for (int j = 0; j < 8; j++) {
        float b1j = b1[d0 + j];
        float w2j = W2[d0 + j];
#pragma unroll
        for (int i = 0; i < 4; i++) {
            float lo, hi; upk2(acc[i][j], lo, hi);
            float h = lo + hi + b1j;
            h = fmaxf(h, 0.f);
            part[i] = fmaf(h, w2j, part[i]);
        }
    }
#pragma unroll
    for (int i = 0; i < 4; i++) red[r0 + i][td] = part[i];
    __syncthreads();

    if (t < 128) {
        float s = b2[0];
#pragma unroll
        for (int k = 0; k < 16; k++) s += red[t][k];
        g_buf[rowBase + t] = s;
    }
}

// =====================================================================
// Kernel B: argmin over one n-half (1024 points) for 1024 vertices.
// grid = 128 blocks = (b:3 | vchunk:3 | nhalf:1), 256 threads,
// 4 vertices/thread packed as 2 f32x2 pairs.
//
// d2 emulates the reference bit-for-bit (assuming fma-contracted einsum):
//   dot  = fma(vz,pz, fma(vy,py, vx*px))          [x,y,z reduce order]
//   d2   = (vv - 2*dot) + pp                      [left-to-right adds]
// Trick: pre-scaling the vertex by -2 is an exact power-of-2 scaling, so
//   fma(-2vz,pz, fma(-2vy,py, (-2vx)*px)) == -2*dot  bitwise.
// Pass 1: fminf per 32-point segment (no index select in hot loop).
// Pass 2: independent first-occurrence min scan of the winning segment.
// =====================================================================
__global__ void __launch_bounds__(256, 1)
kernelB(const float* __restrict__ verts, const float* __restrict__ gpos) {
    __shared__ float pts[1024 * 8];   // per point: {x,x,y,y,z,z,pp,pp}

    const int t = threadIdx.x;
    const int nh = blockIdx.x & 1;
    const int vc = (blockIdx.x >> 1) & 7;
    const int b  = blockIdx.x >> 4;
    const int n0 = nh * 1024;
    const int v0 = vc * 1024;

    // Build duplicated point tile; pp = fma(z,z, fma(y,y, x*x))
    for (int i = t; i < 1024; i += 256) {
        const float* p = gpos + ((size_t)b * N_ + n0 + i) * 3;
        float x = p[0], y = p[1], z = p[2];
        float pn = __fmaf_rn(z, z, __fmaf_rn(y, y, __fmul_rn(x, x)));
        float4* d = (float4*)&pts[i * 8];
        d[0] = make_float4(x, x, y, y);
        d[1] = make_float4(z, z, pn, pn);
    }
    __syncthreads();

    // 4 vertices per thread: v0+t, +256, +512, +768
    float nvx[4], nvy[4], nvz[4], vvq[4];
#pragma unroll
    for (int q = 0; q < 4; q++) {
        const float* vp = verts + ((size_t)b * V_ + v0 + q * 256 + t) * 3;
        float x = vp[0], y = vp[1], z = vp[2];
        nvx[q] = -2.f * x;
        nvy[q] = -2.f * y;
        nvz[q] = -2.f * z;
        vvq[q] = __fmaf_rn(z, z, __fmaf_rn(y, y, __fmul_rn(x, x)));
    }
    const ull X0 = pk2(nvx[0], nvx[1]), Y0 = pk2(nvy[0], nvy[1]), Z0 = pk2(nvz[0], nvz[1]);
    const ull X1 = pk2(nvx[2], nvx[3]), Y1 = pk2(nvy[2], nvy[3]), Z1 = pk2(nvz[2], nvz[3]);
    const ull VV0 = pk2(vvq[0], vvq[1]), VV1 = pk2(vvq[2], vvq[3]);

    const float INF = __int_as_float(0x7f800000);
    float best[4] = {INF, INF, INF, INF};
    int   bseg[4] = {0, 0, 0, 0};

    for (int s = 0; s < 32; s++) {
        float m0 = INF, m1 = INF, m2 = INF, m3 = INF;
        const ulonglong2* base = (const ulonglong2*)&pts[s * 32 * 8];
#pragma unroll 8
        for (int k = 0; k < 32; k++) {
            ulonglong2 a  = base[2 * k];        // {x,x},{y,y}
            ulonglong2 bq = base[2 * k + 1];    // {z,z},{pp,pp}
            // -2*dot (exact scaling), then (vv + m2dot) + pp
            ull s0 = ffma2(Z0, bq.x, ffma2(Y0, a.y, fmul2(X0, a.x)));
            ull s1 = ffma2(Z1, bq.x, ffma2(Y1, a.y, fmul2(X1, a.x)));
            ull d0v = fadd2(fadd2(VV0, s0), bq.y);
            ull d1v = fadd2(fadd2(VV1, s1), bq.y);
            float l0, h0, l1, h1;
            upk2(d0v, l0, h0); upk2(d1v, l1, h1);
            m0 = fminf(m0, l0); m1 = fminf(m1, h0);
            m2 = fminf(m2, l1); m3 = fminf(m3, h1);
        }
        if (m0 < best[0]) { best[0] = m0; bseg[0] = s; }
        if (m1 < best[1]) { best[1] = m1; bseg[1] = s; }
        if (m2 < best[2]) { best[2] = m2; bseg[2] = s; }
        if (m3 < best[3]) { best[3] = m3; bseg[3] = s; }
    }

    // Pass 2: independent first-occurrence min over the winning segment,
    // scalar ops with identical rounding (mul, fma, fma, add, add).
#pragma unroll 1
    for (int q = 0; q < 4; q++) {
        int sbase = bseg[q] * 32;
        float cur = INF;
        int idx = 0;
#pragma unroll 1
        for (int k = 0; k < 32; k++) {
            const float* p = &pts[(sbase + k) * 8];
            float s2 = __fmaf_rn(nvz[q], p[4],
                        __fmaf_rn(nvy[q], p[2],
                         __fmul_rn(nvx[q], p[0])));
            float d2 = __fadd_rn(__fadd_rn(vvq[q], s2), p[6]);
            if (d2 < cur) { cur = d2; idx = k; }
        }
        int o = b * V_ + v0 + q * 256 + t;
        cand_val[nh * (B_ * V_) + o] = best[q];
        cand_idx[nh * (B_ * V_) + o] = n0 + sbase + idx;
    }
}

// =====================================================================
// Kernel C: combine the two n-halves (ties -> half 0 = smaller index,
// matching jnp.argmin first-occurrence) and gather g.
// =====================================================================
__global__ void kernelC(float* __restrict__ out) {
    int i = blockIdx.x * 256 + threadIdx.x;   // 0..65535
    float v0 = cand_val[i];
    float v1 = cand_val[B_ * V_ + i];
    int idx = (v1 < v0) ? cand_idx[B_ * V_ + i] : cand_idx[i];
    int b = i >> 13;
    out[i] = g_buf[b * N_ + idx];
}

// =====================================================================
extern "C" void kernel_launch(void* const* d_in, const int* in_sizes, int n_in,
                              void* d_out, int out_size) {
    const float* verts = (const float*)d_in[0];   // [8,8192,3]
    const float* gpos  = (const float*)d_in[1];   // [8,2048,3]
    const float* proc  = (const float*)d_in[2];   // [8,2048,128]
    const float* W1    = (const float*)d_in[3];   // [128,128]
    const float* b1    = (const float*)d_in[4];   // [128]
    const float* W2    = (const float*)d_in[5];   // [128,1]
    const float* b2    = (const float*)d_in[6];   // [1]
    float* out = (float*)d_out;                   // [8,8192,1]

    cudaFuncSetAttribute(kernelA, cudaFuncAttributeMaxDynamicSharedMemorySize,
                         128 * 128 * 4);

    kernelP<<<32, 256>>>(W1);
    kernelA<<<128, 512, 128 * 128 * 4>>>(proc, b1, W2, b2);
    kernelB<<<128, 256>>>(verts, gpos);
    kernelC<<<256, 256>>>(out);
}